// round 4
// baseline (speedup 1.0000x reference)
#include <cuda_runtime.h>
#include <math.h>

#define BATCH   128
#define DD      128
#define HH      256
#define NBLK_C  256
#define THREADS 1024
#define RBMAX   32
#define SEC     (BATCH*NBLK_C)

typedef unsigned long long u64;

// ---- device scratch (no allocations allowed) ----
__device__ __align__(16) float g_E[BATCH * 511 * DD];
__device__ __align__(16) float g_BP[BATCH * 255 * HH];
__device__ int   g_X[BATCH * 511];
__device__ int   g_U1H[BATCH * 256];
__device__ int   g_fenc[BATCH * NBLK_C];
__device__ __align__(16) float g_Wf[256 * 512];   // [Wc1 | Wb1(top 256 rows)] col-fused
__device__ __align__(16) float g_bf[512];         // [bc1 | bb1]
__device__ __align__(16) float g_emb[2 * HH];     // E_lab[u] @ Wb1[256:384,:]
__device__ __align__(16) float g_w2l[512];        // [Wc2@Wl | Wb2@Wl]
__device__ float g_pbias[2];                      // [bc2@Wl+bl, bb2@Wl+bl]

// ---- f32x2 helpers ----
__device__ __forceinline__ void fma2(u64& acc, u64 a, u64 b) {
    asm("fma.rn.f32x2 %0, %1, %2, %0;" : "+l"(acc) : "l"(a), "l"(b));
}
__device__ __forceinline__ u64 pk2(float x, float y) {
    u64 r; asm("mov.b64 %0, {%1, %2};" : "=l"(r) : "f"(x), "f"(y)); return r;
}
__device__ __forceinline__ float2 upk(u64 v) {
    float2 r; asm("mov.b64 {%0, %1}, %2;" : "=f"(r.x), "=f"(r.y) : "l"(v)); return r;
}

struct Ctx {
    float* Eb; float* BPb; int* Xb; int* U1Hb;
    u64* hs; u64* zs; float* red; float* nh; float* nbp; int* nx;
    const float* Wc2; const float* bc2;
    const float* Wb2; const float* bb2;
    const float* r_in;
    float* u_out; float* p_out;
    int b;
};

// ---------- layer 1 fused: [RB x 256] @ [256 x 512] ----------
// cols 0..255 -> relu -> hs (dup'd f32x2 pairs); cols 256..511 -> bp_out (global)
template<int RB>
__device__ void l1_chunk(const float* __restrict__ Ein, u64* zs, u64* hs,
                         float* __restrict__ bp_out, float* red)
{
    const int t = threadIdx.x;
    if constexpr (RB >= 8) {
        // stage acts, duplicated for f32x2
        for (int idx = t; idx < RB * 128; idx += THREADS) {
            float2 v = ((const float2*)Ein)[idx];
            ulonglong2 d; d.x = pk2(v.x, v.x); d.y = pk2(v.y, v.y);
            ((ulonglong2*)zs)[idx] = d;
        }
        __syncthreads();
        constexpr int NR = RB / 8;
        const int colq = t & 127;
        const int rg   = t >> 7;
        u64 acc[NR][2];
        #pragma unroll
        for (int r = 0; r < NR; r++) { acc[r][0] = 0ull; acc[r][1] = 0ull; }
        const ulonglong2* W = (const ulonglong2*)g_Wf + colq;
        #pragma unroll 2
        for (int k = 0; k < 256; k += 2) {
            ulonglong2 a2[NR];
            #pragma unroll
            for (int r = 0; r < NR; r++)
                a2[r] = *((const ulonglong2*)&zs[(rg + 8 * r) * 256 + k]);
            ulonglong2 w0 = __ldg(W + (size_t)k * 128);
            ulonglong2 w1 = __ldg(W + (size_t)(k + 1) * 128);
            #pragma unroll
            for (int r = 0; r < NR; r++) {
                fma2(acc[r][0], a2[r].x, w0.x); fma2(acc[r][1], a2[r].x, w0.y);
                fma2(acc[r][0], a2[r].y, w1.x); fma2(acc[r][1], a2[r].y, w1.y);
            }
        }
        const int col = colq * 4;
        float4 bias = *((const float4*)&g_bf[col]);
        #pragma unroll
        for (int r = 0; r < NR; r++) {
            int row = rg + 8 * r;
            float2 v0 = upk(acc[r][0]); float2 v1 = upk(acc[r][1]);
            float o0 = v0.x + bias.x, o1 = v0.y + bias.y;
            float o2 = v1.x + bias.z, o3 = v1.y + bias.w;
            if (col < 256) {
                float r0 = fmaxf(o0, 0.f), r1 = fmaxf(o1, 0.f);
                float r2 = fmaxf(o2, 0.f), r3 = fmaxf(o3, 0.f);
                ulonglong2 d0; d0.x = pk2(r0, r0); d0.y = pk2(r1, r1);
                ulonglong2 d1; d1.x = pk2(r2, r2); d1.y = pk2(r3, r3);
                *((ulonglong2*)&hs[row * 256 + col])     = d0;
                *((ulonglong2*)&hs[row * 256 + col + 2]) = d1;
            } else {
                *((float4*)&bp_out[row * HH + (col - 256)]) = make_float4(o0, o1, o2, o3);
            }
        }
        __syncthreads();
    } else {
        // RB = 2 or 4: split-K, acts direct from global
        constexpr int KP = 8 / RB;
        constexpr int KL = 256 / KP;
        const int colq = t & 127;
        const int g    = t >> 7;
        const int r    = g & (RB - 1);
        const int kp   = g / RB;
        const int k0   = kp * KL;
        const float* ac = Ein + r * 256;
        u64 acc0 = 0ull, acc1 = 0ull;
        const ulonglong2* W = (const ulonglong2*)g_Wf + colq;
        #pragma unroll 2
        for (int kb = 0; kb < KL; kb += 4) {
            float4 a4 = __ldg((const float4*)&ac[k0 + kb]);
            ulonglong2 w; u64 a;
            w = __ldg(W + (size_t)(k0 + kb + 0) * 128); a = pk2(a4.x, a4.x); fma2(acc0, a, w.x); fma2(acc1, a, w.y);
            w = __ldg(W + (size_t)(k0 + kb + 1) * 128); a = pk2(a4.y, a4.y); fma2(acc0, a, w.x); fma2(acc1, a, w.y);
            w = __ldg(W + (size_t)(k0 + kb + 2) * 128); a = pk2(a4.z, a4.z); fma2(acc0, a, w.x); fma2(acc1, a, w.y);
            w = __ldg(W + (size_t)(k0 + kb + 3) * 128); a = pk2(a4.w, a4.w); fma2(acc0, a, w.x); fma2(acc1, a, w.y);
        }
        float2 v0 = upk(acc0), v1 = upk(acc1);
        ((float4*)red)[g * 128 + colq] = make_float4(v0.x, v0.y, v1.x, v1.y);
        __syncthreads();
        for (int idx = t; idx < RB * 512; idx += THREADS) {
            int row = idx >> 9, col = idx & 511;
            float v = g_bf[col];
            #pragma unroll
            for (int q = 0; q < KP; q++) v += red[(q * RB + row) * 512 + col];
            if (col < 256) { float rl = fmaxf(v, 0.f); hs[row * 256 + col] = pk2(rl, rl); }
            else bp_out[row * HH + (col - 256)] = v;
        }
        __syncthreads();
    }
}

// ---------- layer 2: [RB x 256] @ [256 x 128] + b2 ----------
template<int RB>
__device__ void l2_chunk(const u64* hs, const float* __restrict__ W2,
                         const float* __restrict__ b2, float* __restrict__ Eout,
                         float* red)
{
    const int t = threadIdx.x;
    const int colq = t & 31;
    const int g    = t >> 5;
    const ulonglong2* W = (const ulonglong2*)W2 + colq;
    if constexpr (RB == 32) {
        const int row = g;
        u64 acc0 = 0ull, acc1 = 0ull;
        #pragma unroll 2
        for (int k = 0; k < 256; k += 2) {
            ulonglong2 a2 = *((const ulonglong2*)&hs[row * 256 + k]);
            ulonglong2 w0 = __ldg(W + (size_t)k * 32);
            ulonglong2 w1 = __ldg(W + (size_t)(k + 1) * 32);
            fma2(acc0, a2.x, w0.x); fma2(acc1, a2.x, w0.y);
            fma2(acc0, a2.y, w1.x); fma2(acc1, a2.y, w1.y);
        }
        float2 v0 = upk(acc0), v1 = upk(acc1);
        const int col = colq * 4;
        float4 bb = *((const float4*)&b2[col]);
        *((float4*)&Eout[row * 128 + col]) =
            make_float4(v0.x + bb.x, v0.y + bb.y, v1.x + bb.z, v1.y + bb.w);
        __syncthreads();
    } else {
        constexpr int KP = 32 / RB;
        constexpr int KL = 256 / KP;
        const int row = g & (RB - 1);
        const int kp  = g / RB;
        const int k0  = kp * KL;
        u64 acc0 = 0ull, acc1 = 0ull;
        #pragma unroll 2
        for (int k = k0; k < k0 + KL; k += 2) {
            ulonglong2 a2 = *((const ulonglong2*)&hs[row * 256 + k]);
            ulonglong2 w0 = __ldg(W + (size_t)k * 32);
            ulonglong2 w1 = __ldg(W + (size_t)(k + 1) * 32);
            fma2(acc0, a2.x, w0.x); fma2(acc1, a2.x, w0.y);
            fma2(acc0, a2.y, w1.x); fma2(acc1, a2.y, w1.y);
        }
        float2 v0 = upk(acc0), v1 = upk(acc1);
        ((float4*)red)[g * 32 + colq] = make_float4(v0.x, v0.y, v1.x, v1.y);
        __syncthreads();
        for (int idx = t; idx < RB * 128; idx += THREADS) {
            int row2 = idx >> 7, col = idx & 127;
            float v = __ldg(&b2[col]);
            #pragma unroll
            for (int q = 0; q < KP; q++) v += red[(q * RB + row2) * 128 + col];
            Eout[row2 * 128 + col] = v;
        }
        __syncthreads();
    }
}

__device__ void check_stage(Ctx& c, int l)
{
    const int half = 1 << (l - 1);
    const float* Ein = c.Eb + ((1 << l) - 1) * DD;
    float* Eout = c.Eb + ((1 << (l - 1)) - 1) * DD;
    float* BPl  = c.BPb + ((1 << (l - 1)) - 1) * HH;
    for (int done = 0; done < half; done += RBMAX) {
        int rbc = half - done; if (rbc > RBMAX) rbc = RBMAX;
        const float* ei = Ein + done * 256;
        float* eo = Eout + done * DD;
        float* bo = BPl + done * HH;
        switch (rbc) {
            case 32: l1_chunk<32>(ei, c.zs, c.hs, bo, c.red); l2_chunk<32>(c.hs, c.Wc2, c.bc2, eo, c.red); break;
            case 16: l1_chunk<16>(ei, c.zs, c.hs, bo, c.red); l2_chunk<16>(c.hs, c.Wc2, c.bc2, eo, c.red); break;
            case 8:  l1_chunk<8 >(ei, c.zs, c.hs, bo, c.red); l2_chunk<8 >(c.hs, c.Wc2, c.bc2, eo, c.red); break;
            case 4:  l1_chunk<4 >(ei, c.zs, c.hs, bo, c.red); l2_chunk<4 >(c.hs, c.Wc2, c.bc2, eo, c.red); break;
            default: l1_chunk<2 >(ei, c.zs, c.hs, bo, c.red); l2_chunk<2 >(c.hs, c.Wc2, c.bc2, eo, c.red); break;
        }
    }
}

__device__ void bit_stage(Ctx& c, int l)
{
    const int half = 1 << (l - 1);
    const int base = (1 << (l - 1)) - 1;
    float* Eout = c.Eb + base * DD;
    const float* BPl = c.BPb + base * HH;
    int* u1h = c.U1Hb + base;
    int* Xlm = c.Xb + base;
    __syncthreads();
    for (int i = threadIdx.x; i < half; i += THREADS) u1h[i] = Xlm[i];
    __syncthreads();
    for (int done = 0; done < half; done += RBMAX) {
        int rbc = half - done; if (rbc > RBMAX) rbc = RBMAX;
        for (int idx = threadIdx.x; idx < rbc * 256; idx += THREADS) {
            int row = idx >> 8, k = idx & 255;
            int u = u1h[done + row];
            float v = fmaxf(BPl[(done + row) * HH + k] + g_emb[u * HH + k], 0.f);
            c.hs[idx] = pk2(v, v);
        }
        __syncthreads();
        float* eo = Eout + done * DD;
        switch (rbc) {
            case 32: l2_chunk<32>(c.hs, c.Wb2, c.bb2, eo, c.red); break;
            case 16: l2_chunk<16>(c.hs, c.Wb2, c.bb2, eo, c.red); break;
            case 8:  l2_chunk<8 >(c.hs, c.Wb2, c.bb2, eo, c.red); break;
            case 4:  l2_chunk<4 >(c.hs, c.Wb2, c.bb2, eo, c.red); break;
            default: l2_chunk<2 >(c.hs, c.Wb2, c.bb2, eo, c.red); break;
        }
    }
}

__device__ __forceinline__ void combine_stage(Ctx& c, int l)
{
    int half = 1 << (l - 1);
    int* u1h = c.U1Hb + ((1 << (l - 1)) - 1);
    int* Xlm = c.Xb + ((1 << (l - 1)) - 1);
    int* Xl  = c.Xb + ((1 << l) - 1);
    __syncthreads();
    for (int i = threadIdx.x; i < half; i += THREADS) {
        int u2 = Xlm[i];
        Xl[2 * i]     = u1h[i] ^ u2;
        Xl[2 * i + 1] = u2;
    }
    __syncthreads();
}

// Fused level-1 node: check-L1 -> p_left -> left leaf -> bit-hidden -> p_right
// -> right leaf -> combine(1). No layer-2 GEMMs needed (dots vs W2@Wl).
__device__ void node1(Ctx& c, int n)
{
    const int t = threadIdx.x;
    const float* Ein = c.Eb + DD;   // level-1 array (2 rows) at base 1
    const int colq = t & 127;
    const int kp   = t >> 7;
    const int k0   = kp * 32;
    u64 acc0 = 0ull, acc1 = 0ull;
    const ulonglong2* W = (const ulonglong2*)g_Wf + colq;
    #pragma unroll
    for (int kb = 0; kb < 32; kb += 4) {
        float4 a4 = __ldg((const float4*)&Ein[k0 + kb]);
        ulonglong2 w; u64 a;
        w = __ldg(W + (size_t)(k0 + kb + 0) * 128); a = pk2(a4.x, a4.x); fma2(acc0, a, w.x); fma2(acc1, a, w.y);
        w = __ldg(W + (size_t)(k0 + kb + 1) * 128); a = pk2(a4.y, a4.y); fma2(acc0, a, w.x); fma2(acc1, a, w.y);
        w = __ldg(W + (size_t)(k0 + kb + 2) * 128); a = pk2(a4.z, a4.z); fma2(acc0, a, w.x); fma2(acc1, a, w.y);
        w = __ldg(W + (size_t)(k0 + kb + 3) * 128); a = pk2(a4.w, a4.w); fma2(acc0, a, w.x); fma2(acc1, a, w.y);
    }
    float2 v0 = upk(acc0), v1 = upk(acc1);
    ((float4*)c.red)[kp * 128 + colq] = make_float4(v0.x, v0.y, v1.x, v1.y);
    __syncthreads();
    if (t < 512) {
        float v = g_bf[t];
        #pragma unroll
        for (int q = 0; q < 8; q++) v += c.red[q * 512 + t];
        if (t < 256) c.nh[t] = fmaxf(v, 0.f);
        else c.nbp[t - 256] = v;
    }
    __syncthreads();
    if (t < 32) {
        float s = 0.f;
        #pragma unroll
        for (int j = 0; j < 8; j++) s = fmaf(c.nh[t + 32 * j], g_w2l[t + 32 * j], s);
        #pragma unroll
        for (int o = 16; o > 0; o >>= 1) s += __shfl_xor_sync(0xffffffffu, s, o);
        if (t == 0) {
            float p = 1.f / (1.f + expf(-(s + g_pbias[0])));
            int leaf = 2 * n;
            float rv = __ldg(&c.r_in[c.b * NBLK_C + leaf]);
            int f  = g_fenc[c.b * NBLK_C + leaf];
            int hd = (rv > p) ? 1 : 0;
            int x  = ((f == 2) || (fabsf(p - 0.5f) > 0.25f)) ? hd : f;
            *c.nx = x;
            c.u_out[c.b * NBLK_C + leaf] = (float)x;
            c.p_out[c.b * NBLK_C + leaf] = p;
        }
    }
    __syncthreads();
    int xL = *c.nx;
    if (t < 256)
        c.red[t] = fmaxf(c.nbp[t] + g_emb[xL * HH + t], 0.f) * g_w2l[256 + t];
    __syncthreads();
    if (t < 32) {
        float s = 0.f;
        #pragma unroll
        for (int j = 0; j < 8; j++) s += c.red[t + 32 * j];
        #pragma unroll
        for (int o = 16; o > 0; o >>= 1) s += __shfl_xor_sync(0xffffffffu, s, o);
        if (t == 0) {
            float p = 1.f / (1.f + expf(-(s + g_pbias[1])));
            int leaf = 2 * n + 1;
            float rv = __ldg(&c.r_in[c.b * NBLK_C + leaf]);
            int f  = g_fenc[c.b * NBLK_C + leaf];
            int hd = (rv > p) ? 1 : 0;
            int xR = ((f == 2) || (fabsf(p - 0.5f) > 0.25f)) ? hd : f;
            c.u_out[c.b * NBLK_C + leaf] = (float)xR;
            c.p_out[c.b * NBLK_C + leaf] = p;
            c.Xb[1] = xL ^ xR;   // combine(1)
            c.Xb[2] = xR;
        }
    }
    __syncthreads();
}

__global__ void __launch_bounds__(THREADS, 1)
sc_main(const float* r_in,
        const float* Wc2, const float* bc2,
        const float* Wb2, const float* bb2,
        float* out)
{
    extern __shared__ __align__(16) char smraw[];
    Ctx c;
    c.hs  = (u64*)smraw;                     // 64 KB
    c.zs  = c.hs + 32 * 256;                 // 64 KB
    c.red = (float*)(c.zs + 32 * 256);       // 16 KB
    c.nh  = c.red + 4096;
    c.nbp = c.nh + 256;
    c.nx  = (int*)(c.nbp + 256);
    c.b = blockIdx.x;
    c.Eb   = g_E   + c.b * 511 * DD;
    c.BPb  = g_BP  + c.b * 255 * HH;
    c.Xb   = g_X   + c.b * 511;
    c.U1Hb = g_U1H + c.b * 256;
    c.Wc2 = Wc2; c.bc2 = bc2;
    c.Wb2 = Wb2; c.bb2 = bb2;
    c.r_in  = r_in;
    c.u_out = out + 2 * SEC;
    c.p_out = out + 3 * SEC;

    for (int l = 8; l >= 2; l--) check_stage(c, l);
    for (int n = 0; n < 128; n++) {
        node1(c, n);
        if (n == 127) break;
        int l = 2;
        while ((n >> (l - 2)) & 1) { combine_stage(c, l); l++; }
        bit_stage(c, l);
        for (int ld = l - 1; ld >= 2; ld--) check_stage(c, ld);
    }
    for (int l = 2; l <= 8; l++) combine_stage(c, l);

    int* X8 = c.Xb + 255;
    for (int i = threadIdx.x; i < NBLK_C; i += THREADS)
        out[c.b * NBLK_C + i] = (float)X8[i];
}

// ---- per-batch init ----
__global__ void sc_setup(const int* info_bits, const float* r_in, const int* info_set,
                         const float* E_obs, float* out)
{
    int b = blockIdx.x, t = threadIdx.x;
    for (int j = t; j < NBLK_C; j += blockDim.x) {
        g_fenc[b * NBLK_C + j] = 2;
        out[1 * SEC + b * NBLK_C + j] = 1.0f;
        out[4 * SEC + b * NBLK_C + j] = r_in[b * NBLK_C + j];
    }
    __syncthreads();
    for (int k = t; k < 128; k += blockDim.x) {
        int pos = info_set[k];
        g_fenc[b * NBLK_C + pos] = info_bits[b * 128 + k];
        out[1 * SEC + b * NBLK_C + pos] = 2.0f;
    }
    for (int idx = t; idx < 256 * DD; idx += blockDim.x) {
        int i = idx >> 7, k = idx & (DD - 1);
        g_E[b * 511 * DD + (255 + i) * DD + k] = E_obs[2 * DD + k];
    }
}

// ---- parallel weight prep ----
__global__ void sc_prep(const float* Wc1, const float* bc1,
                        const float* Wb1, const float* bb1,
                        const float* E_lab,
                        const float* Wc2, const float* bc2,
                        const float* Wb2, const float* bb2,
                        const float* Wl, const float* bl)
{
    int tid = blockIdx.x * blockDim.x + threadIdx.x;   // 64*512 = 32768 threads
    {   // g_Wf: 32768 float4 copies
        int k = tid >> 7, c4 = (tid & 127) * 4;
        float4 v;
        if (c4 < 256) v = *((const float4*)&Wc1[k * 256 + c4]);
        else          v = *((const float4*)&Wb1[k * 256 + (c4 - 256)]);
        *((float4*)&g_Wf[k * 512 + c4]) = v;
    }
    if (tid < 512) g_bf[tid] = (tid < 256) ? bc1[tid] : bb1[tid - 256];
    if (tid >= 512 && tid < 1024) {
        int cidx = tid - 512;
        const float* W2 = (cidx < 256) ? Wc2 : Wb2;
        int k = cidx & 255;
        float s = 0.f;
        for (int d = 0; d < 128; d++) s += W2[k * 128 + d] * Wl[d];
        g_w2l[cidx] = s;
    }
    if (tid >= 1024 && tid < 1536) {
        int cidx = tid - 1024; int u = cidx >> 8, j = cidx & 255;
        float s = 0.f;
        for (int d = 0; d < 128; d++) s += E_lab[u * 128 + d] * Wb1[(256 + d) * 256 + j];
        g_emb[u * HH + j] = s;
    }
    if (tid == 1536 || tid == 1537) {
        int u = tid - 1536;
        const float* b2 = u ? bb2 : bc2;
        float s = bl[0];
        for (int d = 0; d < 128; d++) s += b2[d] * Wl[d];
        g_pbias[u] = s;
    }
}

extern "C" void kernel_launch(void* const* d_in, const int* in_sizes, int n_in,
                              void* d_out, int out_size)
{
    const int*   info_bits = (const int*)  d_in[0];
    const float* r_in      = (const float*)d_in[1];
    const int*   info_set  = (const int*)  d_in[2];
    const float* E_obs     = (const float*)d_in[3];
    const float* E_lab     = (const float*)d_in[4];
    const float* Wc1 = (const float*)d_in[5];
    const float* bc1 = (const float*)d_in[6];
    const float* Wc2 = (const float*)d_in[7];
    const float* bc2 = (const float*)d_in[8];
    const float* Wb1 = (const float*)d_in[9];
    const float* bb1 = (const float*)d_in[10];
    const float* Wb2 = (const float*)d_in[11];
    const float* bb2 = (const float*)d_in[12];
    const float* Wl  = (const float*)d_in[13];
    const float* bl  = (const float*)d_in[14];
    float* out = (float*)d_out;

    const int smem = (32 * 256 * 8) * 2 + 4096 * 4 + 2 * 256 * 4 + 16;  // ~147.5 KB
    cudaFuncSetAttribute(sc_main, cudaFuncAttributeMaxDynamicSharedMemorySize, smem);

    sc_prep<<<64, 512>>>(Wc1, bc1, Wb1, bb1, E_lab, Wc2, bc2, Wb2, bb2, Wl, bl);
    sc_setup<<<BATCH, 256>>>(info_bits, r_in, info_set, E_obs, out);
    sc_main<<<BATCH, THREADS, smem>>>(r_in, Wc2, bc2, Wb2, bb2, out);
}

// round 5
// speedup vs baseline: 1.0529x; 1.0529x over previous
#include <cuda_runtime.h>
#include <math.h>

#define BATCH   128
#define DD      128
#define HH      256
#define NBLK_C  256
#define THREADS 1024
#define RBMAX   32
#define SEC     (BATCH*NBLK_C)

typedef unsigned long long u64;

// ---- device scratch (no allocations allowed) ----
__device__ __align__(16) float g_E[BATCH * 511 * DD];
__device__ __align__(16) float g_BP[BATCH * 255 * HH];
__device__ int   g_X[BATCH * 511];
__device__ int   g_U1H[BATCH * 256];
__device__ int   g_fenc[BATCH * NBLK_C];
__device__ __align__(16) float g_Wf[256 * 512];   // [Wc1 | Wb1(top 256 rows)] col-fused
__device__ __align__(16) float g_bf[512];         // [bc1 | bb1]
__device__ __align__(16) float g_emb[2 * HH];     // E_lab[u] @ Wb1[256:384,:]
__device__ __align__(16) float g_w2l[512];        // [Wc2@Wl | Wb2@Wl]
__device__ float g_pbias[2];                      // [bc2@Wl+bl, bb2@Wl+bl]

// ---- f32x2 helpers ----
__device__ __forceinline__ void fma2(u64& acc, u64 a, u64 b) {
    asm("fma.rn.f32x2 %0, %1, %2, %0;" : "+l"(acc) : "l"(a), "l"(b));
}
__device__ __forceinline__ u64 pk2(float x, float y) {
    u64 r; asm("mov.b64 %0, {%1, %2};" : "=l"(r) : "f"(x), "f"(y)); return r;
}
__device__ __forceinline__ float2 upk(u64 v) {
    float2 r; asm("mov.b64 {%0, %1}, %2;" : "=f"(r.x), "=f"(r.y) : "l"(v)); return r;
}

struct Ctx {
    float* Eb; float* BPb; int* Xb; int* U1Hb;
    u64* hs; u64* zs; float* red; float* nh; float* nbp; int* nx;
    const float* Wc2; const float* bc2;
    const float* Wb2; const float* bb2;
    const float* r_in;
    float* u_out; float* p_out;
    int b;
};

// ---------- layer 1 fused: [RB x 256] @ [256 x 512] ----------
// cols 0..255 -> relu -> hs (dup'd f32x2 pairs); cols 256..511 -> bp_out (global)
template<int RB>
__device__ void l1_chunk(const float* __restrict__ Ein, u64* zs, u64* hs,
                         float* __restrict__ bp_out, float* red)
{
    const int t = threadIdx.x;
    if constexpr (RB >= 8) {
        // stage acts, duplicated for f32x2
        for (int idx = t; idx < RB * 128; idx += THREADS) {
            float2 v = ((const float2*)Ein)[idx];
            ulonglong2 d; d.x = pk2(v.x, v.x); d.y = pk2(v.y, v.y);
            ((ulonglong2*)zs)[idx] = d;
        }
        __syncthreads();
        constexpr int NR = RB / 8;
        const int colq = t & 127;
        const int rg   = t >> 7;
        u64 acc[NR][2];
        #pragma unroll
        for (int r = 0; r < NR; r++) { acc[r][0] = 0ull; acc[r][1] = 0ull; }
        const ulonglong2* W = (const ulonglong2*)g_Wf + colq;
        #pragma unroll 2
        for (int k = 0; k < 256; k += 2) {
            ulonglong2 a2[NR];
            #pragma unroll
            for (int r = 0; r < NR; r++)
                a2[r] = *((const ulonglong2*)&zs[(rg + 8 * r) * 256 + k]);
            ulonglong2 w0 = __ldg(W + (size_t)k * 128);
            ulonglong2 w1 = __ldg(W + (size_t)(k + 1) * 128);
            #pragma unroll
            for (int r = 0; r < NR; r++) {
                fma2(acc[r][0], a2[r].x, w0.x); fma2(acc[r][1], a2[r].x, w0.y);
                fma2(acc[r][0], a2[r].y, w1.x); fma2(acc[r][1], a2[r].y, w1.y);
            }
        }
        const int col = colq * 4;
        float4 bias = *((const float4*)&g_bf[col]);
        #pragma unroll
        for (int r = 0; r < NR; r++) {
            int row = rg + 8 * r;
            float2 v0 = upk(acc[r][0]); float2 v1 = upk(acc[r][1]);
            float o0 = v0.x + bias.x, o1 = v0.y + bias.y;
            float o2 = v1.x + bias.z, o3 = v1.y + bias.w;
            if (col < 256) {
                float r0 = fmaxf(o0, 0.f), r1 = fmaxf(o1, 0.f);
                float r2 = fmaxf(o2, 0.f), r3 = fmaxf(o3, 0.f);
                ulonglong2 d0; d0.x = pk2(r0, r0); d0.y = pk2(r1, r1);
                ulonglong2 d1; d1.x = pk2(r2, r2); d1.y = pk2(r3, r3);
                *((ulonglong2*)&hs[row * 256 + col])     = d0;
                *((ulonglong2*)&hs[row * 256 + col + 2]) = d1;
            } else {
                *((float4*)&bp_out[row * HH + (col - 256)]) = make_float4(o0, o1, o2, o3);
            }
        }
        __syncthreads();
    } else {
        // RB = 2 or 4: split-K, acts direct from global
        constexpr int KP = 8 / RB;
        constexpr int KL = 256 / KP;
        const int colq = t & 127;
        const int g    = t >> 7;
        const int r    = g & (RB - 1);
        const int kp   = g / RB;
        const int k0   = kp * KL;
        const float* ac = Ein + r * 256;
        u64 acc0 = 0ull, acc1 = 0ull;
        const ulonglong2* W = (const ulonglong2*)g_Wf + colq;
        #pragma unroll 2
        for (int kb = 0; kb < KL; kb += 4) {
            float4 a4 = __ldg((const float4*)&ac[k0 + kb]);
            ulonglong2 w; u64 a;
            w = __ldg(W + (size_t)(k0 + kb + 0) * 128); a = pk2(a4.x, a4.x); fma2(acc0, a, w.x); fma2(acc1, a, w.y);
            w = __ldg(W + (size_t)(k0 + kb + 1) * 128); a = pk2(a4.y, a4.y); fma2(acc0, a, w.x); fma2(acc1, a, w.y);
            w = __ldg(W + (size_t)(k0 + kb + 2) * 128); a = pk2(a4.z, a4.z); fma2(acc0, a, w.x); fma2(acc1, a, w.y);
            w = __ldg(W + (size_t)(k0 + kb + 3) * 128); a = pk2(a4.w, a4.w); fma2(acc0, a, w.x); fma2(acc1, a, w.y);
        }
        float2 v0 = upk(acc0), v1 = upk(acc1);
        ((float4*)red)[g * 128 + colq] = make_float4(v0.x, v0.y, v1.x, v1.y);
        __syncthreads();
        for (int idx = t; idx < RB * 512; idx += THREADS) {
            int row = idx >> 9, col = idx & 511;
            float v = g_bf[col];
            #pragma unroll
            for (int q = 0; q < KP; q++) v += red[(q * RB + row) * 512 + col];
            if (col < 256) { float rl = fmaxf(v, 0.f); hs[row * 256 + col] = pk2(rl, rl); }
            else bp_out[row * HH + (col - 256)] = v;
        }
        __syncthreads();
    }
}

// ---------- layer 2: [RB x 256] @ [256 x 128] + b2 ----------
template<int RB>
__device__ void l2_chunk(const u64* hs, const float* __restrict__ W2,
                         const float* __restrict__ b2, float* __restrict__ Eout,
                         float* red)
{
    const int t = threadIdx.x;
    const int colq = t & 31;
    const int g    = t >> 5;
    const ulonglong2* W = (const ulonglong2*)W2 + colq;
    if constexpr (RB == 32) {
        const int row = g;
        u64 acc0 = 0ull, acc1 = 0ull;
        #pragma unroll 2
        for (int k = 0; k < 256; k += 2) {
            ulonglong2 a2 = *((const ulonglong2*)&hs[row * 256 + k]);
            ulonglong2 w0 = __ldg(W + (size_t)k * 32);
            ulonglong2 w1 = __ldg(W + (size_t)(k + 1) * 32);
            fma2(acc0, a2.x, w0.x); fma2(acc1, a2.x, w0.y);
            fma2(acc0, a2.y, w1.x); fma2(acc1, a2.y, w1.y);
        }
        float2 v0 = upk(acc0), v1 = upk(acc1);
        const int col = colq * 4;
        float4 bb = *((const float4*)&b2[col]);
        *((float4*)&Eout[row * 128 + col]) =
            make_float4(v0.x + bb.x, v0.y + bb.y, v1.x + bb.z, v1.y + bb.w);
        __syncthreads();
    } else {
        constexpr int KP = 32 / RB;
        constexpr int KL = 256 / KP;
        const int row = g & (RB - 1);
        const int kp  = g / RB;
        const int k0  = kp * KL;
        u64 acc0 = 0ull, acc1 = 0ull;
        #pragma unroll 2
        for (int k = k0; k < k0 + KL; k += 2) {
            ulonglong2 a2 = *((const ulonglong2*)&hs[row * 256 + k]);
            ulonglong2 w0 = __ldg(W + (size_t)k * 32);
            ulonglong2 w1 = __ldg(W + (size_t)(k + 1) * 32);
            fma2(acc0, a2.x, w0.x); fma2(acc1, a2.x, w0.y);
            fma2(acc0, a2.y, w1.x); fma2(acc1, a2.y, w1.y);
        }
        float2 v0 = upk(acc0), v1 = upk(acc1);
        ((float4*)red)[g * 32 + colq] = make_float4(v0.x, v0.y, v1.x, v1.y);
        __syncthreads();
        for (int idx = t; idx < RB * 128; idx += THREADS) {
            int row2 = idx >> 7, col = idx & 127;
            float v = __ldg(&b2[col]);
            #pragma unroll
            for (int q = 0; q < KP; q++) v += red[(q * RB + row2) * 128 + col];
            Eout[row2 * 128 + col] = v;
        }
        __syncthreads();
    }
}

__device__ void check_stage(Ctx& c, int l)
{
    const int half = 1 << (l - 1);
    const float* Ein = c.Eb + ((1 << l) - 1) * DD;
    float* Eout = c.Eb + ((1 << (l - 1)) - 1) * DD;
    float* BPl  = c.BPb + ((1 << (l - 1)) - 1) * HH;
    for (int done = 0; done < half; done += RBMAX) {
        int rbc = half - done; if (rbc > RBMAX) rbc = RBMAX;
        const float* ei = Ein + done * 256;
        float* eo = Eout + done * DD;
        float* bo = BPl + done * HH;
        switch (rbc) {
            case 32: l1_chunk<32>(ei, c.zs, c.hs, bo, c.red); l2_chunk<32>(c.hs, c.Wc2, c.bc2, eo, c.red); break;
            case 16: l1_chunk<16>(ei, c.zs, c.hs, bo, c.red); l2_chunk<16>(c.hs, c.Wc2, c.bc2, eo, c.red); break;
            case 8:  l1_chunk<8 >(ei, c.zs, c.hs, bo, c.red); l2_chunk<8 >(c.hs, c.Wc2, c.bc2, eo, c.red); break;
            case 4:  l1_chunk<4 >(ei, c.zs, c.hs, bo, c.red); l2_chunk<4 >(c.hs, c.Wc2, c.bc2, eo, c.red); break;
            default: l1_chunk<2 >(ei, c.zs, c.hs, bo, c.red); l2_chunk<2 >(c.hs, c.Wc2, c.bc2, eo, c.red); break;
        }
    }
}

__device__ void bit_stage(Ctx& c, int l)
{
    const int half = 1 << (l - 1);
    const int base = (1 << (l - 1)) - 1;
    float* Eout = c.Eb + base * DD;
    const float* BPl = c.BPb + base * HH;
    int* u1h = c.U1Hb + base;
    int* Xlm = c.Xb + base;
    __syncthreads();
    for (int i = threadIdx.x; i < half; i += THREADS) u1h[i] = Xlm[i];
    __syncthreads();
    for (int done = 0; done < half; done += RBMAX) {
        int rbc = half - done; if (rbc > RBMAX) rbc = RBMAX;
        for (int idx = threadIdx.x; idx < rbc * 256; idx += THREADS) {
            int row = idx >> 8, k = idx & 255;
            int u = u1h[done + row];
            float v = fmaxf(BPl[(done + row) * HH + k] + g_emb[u * HH + k], 0.f);
            c.hs[idx] = pk2(v, v);
        }
        __syncthreads();
        float* eo = Eout + done * DD;
        switch (rbc) {
            case 32: l2_chunk<32>(c.hs, c.Wb2, c.bb2, eo, c.red); break;
            case 16: l2_chunk<16>(c.hs, c.Wb2, c.bb2, eo, c.red); break;
            case 8:  l2_chunk<8 >(c.hs, c.Wb2, c.bb2, eo, c.red); break;
            case 4:  l2_chunk<4 >(c.hs, c.Wb2, c.bb2, eo, c.red); break;
            default: l2_chunk<2 >(c.hs, c.Wb2, c.bb2, eo, c.red); break;
        }
    }
}

__device__ __forceinline__ void combine_stage(Ctx& c, int l)
{
    int half = 1 << (l - 1);
    int* u1h = c.U1Hb + ((1 << (l - 1)) - 1);
    int* Xlm = c.Xb + ((1 << (l - 1)) - 1);
    int* Xl  = c.Xb + ((1 << l) - 1);
    __syncthreads();
    for (int i = threadIdx.x; i < half; i += THREADS) {
        int u2 = Xlm[i];
        Xl[2 * i]     = u1h[i] ^ u2;
        Xl[2 * i + 1] = u2;
    }
    __syncthreads();
}

// Fused level-1 node: check-L1 -> p_left -> left leaf -> bit-hidden -> p_right
// -> right leaf -> combine(1). No layer-2 GEMMs needed (dots vs W2@Wl).
__device__ void node1(Ctx& c, int n)
{
    const int t = threadIdx.x;
    const float* Ein = c.Eb + DD;   // level-1 array (2 rows) at base 1
    const int colq = t & 127;
    const int kp   = t >> 7;
    const int k0   = kp * 32;
    u64 acc0 = 0ull, acc1 = 0ull;
    const ulonglong2* W = (const ulonglong2*)g_Wf + colq;
    #pragma unroll
    for (int kb = 0; kb < 32; kb += 4) {
        float4 a4 = __ldg((const float4*)&Ein[k0 + kb]);
        ulonglong2 w; u64 a;
        w = __ldg(W + (size_t)(k0 + kb + 0) * 128); a = pk2(a4.x, a4.x); fma2(acc0, a, w.x); fma2(acc1, a, w.y);
        w = __ldg(W + (size_t)(k0 + kb + 1) * 128); a = pk2(a4.y, a4.y); fma2(acc0, a, w.x); fma2(acc1, a, w.y);
        w = __ldg(W + (size_t)(k0 + kb + 2) * 128); a = pk2(a4.z, a4.z); fma2(acc0, a, w.x); fma2(acc1, a, w.y);
        w = __ldg(W + (size_t)(k0 + kb + 3) * 128); a = pk2(a4.w, a4.w); fma2(acc0, a, w.x); fma2(acc1, a, w.y);
    }
    float2 v0 = upk(acc0), v1 = upk(acc1);
    ((float4*)c.red)[kp * 128 + colq] = make_float4(v0.x, v0.y, v1.x, v1.y);
    __syncthreads();
    if (t < 512) {
        float v = g_bf[t];
        #pragma unroll
        for (int q = 0; q < 8; q++) v += c.red[q * 512 + t];
        if (t < 256) c.nh[t] = fmaxf(v, 0.f);
        else c.nbp[t - 256] = v;
    }
    __syncthreads();
    if (t < 32) {
        float s = 0.f;
        #pragma unroll
        for (int j = 0; j < 8; j++) s = fmaf(c.nh[t + 32 * j], g_w2l[t + 32 * j], s);
        #pragma unroll
        for (int o = 16; o > 0; o >>= 1) s += __shfl_xor_sync(0xffffffffu, s, o);
        if (t == 0) {
            float p = 1.f / (1.f + expf(-(s + g_pbias[0])));
            int leaf = 2 * n;
            float rv = __ldg(&c.r_in[c.b * NBLK_C + leaf]);
            int f  = g_fenc[c.b * NBLK_C + leaf];
            int hd = (rv > p) ? 1 : 0;
            int x  = ((f == 2) || (fabsf(p - 0.5f) > 0.25f)) ? hd : f;
            *c.nx = x;
            c.u_out[c.b * NBLK_C + leaf] = (float)x;
            c.p_out[c.b * NBLK_C + leaf] = p;
        }
    }
    __syncthreads();
    int xL = *c.nx;
    if (t < 256)
        c.red[t] = fmaxf(c.nbp[t] + g_emb[xL * HH + t], 0.f) * g_w2l[256 + t];
    __syncthreads();
    if (t < 32) {
        float s = 0.f;
        #pragma unroll
        for (int j = 0; j < 8; j++) s += c.red[t + 32 * j];
        #pragma unroll
        for (int o = 16; o > 0; o >>= 1) s += __shfl_xor_sync(0xffffffffu, s, o);
        if (t == 0) {
            float p = 1.f / (1.f + expf(-(s + g_pbias[1])));
            int leaf = 2 * n + 1;
            float rv = __ldg(&c.r_in[c.b * NBLK_C + leaf]);
            int f  = g_fenc[c.b * NBLK_C + leaf];
            int hd = (rv > p) ? 1 : 0;
            int xR = ((f == 2) || (fabsf(p - 0.5f) > 0.25f)) ? hd : f;
            c.u_out[c.b * NBLK_C + leaf] = (float)xR;
            c.p_out[c.b * NBLK_C + leaf] = p;
            c.Xb[1] = xL ^ xR;   // combine(1)
            c.Xb[2] = xR;
        }
    }
    __syncthreads();
}

__global__ void __launch_bounds__(THREADS, 1)
sc_main(const float* r_in,
        const float* Wc2, const float* bc2,
        const float* Wb2, const float* bb2,
        float* out)
{
    extern __shared__ __align__(16) char smraw[];
    Ctx c;
    c.hs  = (u64*)smraw;                     // 64 KB
    c.zs  = c.hs + 32 * 256;                 // 64 KB
    c.red = (float*)(c.zs + 32 * 256);       // 16 KB
    c.nh  = c.red + 4096;
    c.nbp = c.nh + 256;
    c.nx  = (int*)(c.nbp + 256);
    c.b = blockIdx.x;
    c.Eb   = g_E   + c.b * 511 * DD;
    c.BPb  = g_BP  + c.b * 255 * HH;
    c.Xb   = g_X   + c.b * 511;
    c.U1Hb = g_U1H + c.b * 256;
    c.Wc2 = Wc2; c.bc2 = bc2;
    c.Wb2 = Wb2; c.bb2 = bb2;
    c.r_in  = r_in;
    c.u_out = out + 2 * SEC;
    c.p_out = out + 3 * SEC;

    for (int l = 8; l >= 2; l--) check_stage(c, l);
    for (int n = 0; n < 128; n++) {
        node1(c, n);
        if (n == 127) break;
        int l = 2;
        while ((n >> (l - 2)) & 1) { combine_stage(c, l); l++; }
        bit_stage(c, l);
        for (int ld = l - 1; ld >= 2; ld--) check_stage(c, ld);
    }
    for (int l = 2; l <= 8; l++) combine_stage(c, l);

    int* X8 = c.Xb + 255;
    for (int i = threadIdx.x; i < NBLK_C; i += THREADS)
        out[c.b * NBLK_C + i] = (float)X8[i];
}

// ---- per-batch init ----
__global__ void sc_setup(const int* info_bits, const float* r_in, const int* info_set,
                         const float* E_obs, float* out)
{
    int b = blockIdx.x, t = threadIdx.x;
    for (int j = t; j < NBLK_C; j += blockDim.x) {
        g_fenc[b * NBLK_C + j] = 2;
        out[1 * SEC + b * NBLK_C + j] = 1.0f;
        out[4 * SEC + b * NBLK_C + j] = r_in[b * NBLK_C + j];
    }
    __syncthreads();
    for (int k = t; k < 128; k += blockDim.x) {
        int pos = info_set[k];
        g_fenc[b * NBLK_C + pos] = info_bits[b * 128 + k];
        out[1 * SEC + b * NBLK_C + pos] = 2.0f;
    }
    for (int idx = t; idx < 256 * DD; idx += blockDim.x) {
        int i = idx >> 7, k = idx & (DD - 1);
        g_E[b * 511 * DD + (255 + i) * DD + k] = E_obs[2 * DD + k];
    }
}

// ---- parallel weight prep ----
__global__ void sc_prep(const float* Wc1, const float* bc1,
                        const float* Wb1, const float* bb1,
                        const float* E_lab,
                        const float* Wc2, const float* bc2,
                        const float* Wb2, const float* bb2,
                        const float* Wl, const float* bl)
{
    int tid = blockIdx.x * blockDim.x + threadIdx.x;   // 64*512 = 32768 threads
    {   // g_Wf: 32768 float4 copies
        int k = tid >> 7, c4 = (tid & 127) * 4;
        float4 v;
        if (c4 < 256) v = *((const float4*)&Wc1[k * 256 + c4]);
        else          v = *((const float4*)&Wb1[k * 256 + (c4 - 256)]);
        *((float4*)&g_Wf[k * 512 + c4]) = v;
    }
    if (tid < 512) g_bf[tid] = (tid < 256) ? bc1[tid] : bb1[tid - 256];
    if (tid >= 512 && tid < 1024) {
        int cidx = tid - 512;
        const float* W2 = (cidx < 256) ? Wc2 : Wb2;
        int k = cidx & 255;
        float s = 0.f;
        for (int d = 0; d < 128; d++) s += W2[k * 128 + d] * Wl[d];
        g_w2l[cidx] = s;
    }
    if (tid >= 1024 && tid < 1536) {
        int cidx = tid - 1024; int u = cidx >> 8, j = cidx & 255;
        float s = 0.f;
        for (int d = 0; d < 128; d++) s += E_lab[u * 128 + d] * Wb1[(256 + d) * 256 + j];
        g_emb[u * HH + j] = s;
    }
    if (tid == 1536 || tid == 1537) {
        int u = tid - 1536;
        const float* b2 = u ? bb2 : bc2;
        float s = bl[0];
        for (int d = 0; d < 128; d++) s += b2[d] * Wl[d];
        g_pbias[u] = s;
    }
}

extern "C" void kernel_launch(void* const* d_in, const int* in_sizes, int n_in,
                              void* d_out, int out_size)
{
    const int*   info_bits = (const int*)  d_in[0];
    const float* r_in      = (const float*)d_in[1];
    const int*   info_set  = (const int*)  d_in[2];
    const float* E_obs     = (const float*)d_in[3];
    const float* E_lab     = (const float*)d_in[4];
    const float* Wc1 = (const float*)d_in[5];
    const float* bc1 = (const float*)d_in[6];
    const float* Wc2 = (const float*)d_in[7];
    const float* bc2 = (const float*)d_in[8];
    const float* Wb1 = (const float*)d_in[9];
    const float* bb1 = (const float*)d_in[10];
    const float* Wb2 = (const float*)d_in[11];
    const float* bb2 = (const float*)d_in[12];
    const float* Wl  = (const float*)d_in[13];
    const float* bl  = (const float*)d_in[14];
    float* out = (float*)d_out;

    const int smem = (32 * 256 * 8) * 2 + 4096 * 4 + 2 * 256 * 4 + 16;  // ~147.5 KB
    cudaFuncSetAttribute(sc_main, cudaFuncAttributeMaxDynamicSharedMemorySize, smem);

    sc_prep<<<64, 512>>>(Wc1, bc1, Wb1, bb1, E_lab, Wc2, bc2, Wb2, bb2, Wl, bl);
    sc_setup<<<BATCH, 256>>>(info_bits, r_in, info_set, E_obs, out);
    sc_main<<<BATCH, THREADS, smem>>>(r_in, Wc2, bc2, Wb2, bb2, out);
}

// round 6
// speedup vs baseline: 1.0542x; 1.0012x over previous
#include <cuda_runtime.h>
#include <math.h>

#define BATCH   128
#define DD      128
#define HH      256
#define NBLK_C  256
#define THREADS 1024
#define RBMAX   32
#define SEC     (BATCH*NBLK_C)

typedef unsigned long long u64;

// ---- device scratch (no allocations allowed) ----
__device__ __align__(16) float g_E[BATCH * 511 * DD];
__device__ __align__(16) float g_BP[BATCH * 255 * HH];
__device__ int   g_X[BATCH * 511];
__device__ int   g_U1H[BATCH * 256];
__device__ int   g_fenc[BATCH * NBLK_C];
__device__ __align__(16) float g_Wf[256 * 512];   // [Wc1 | Wb1(top 256 rows)] col-fused
__device__ __align__(16) float g_bf[512];         // [bc1 | bb1]
__device__ __align__(16) float g_emb[2 * HH];     // E_lab[u] @ Wb1[256:384,:]
__device__ __align__(16) float g_w2l[512];        // [Wc2@Wl | Wb2@Wl]
__device__ float g_pbias[2];                      // [bc2@Wl+bl, bb2@Wl+bl]

// ---- f32x2 helpers ----
__device__ __forceinline__ void fma2(u64& acc, u64 a, u64 b) {
    asm("fma.rn.f32x2 %0, %1, %2, %0;" : "+l"(acc) : "l"(a), "l"(b));
}
__device__ __forceinline__ u64 pk2(float x, float y) {
    u64 r; asm("mov.b64 %0, {%1, %2};" : "=l"(r) : "f"(x), "f"(y)); return r;
}
__device__ __forceinline__ float2 upk(u64 v) {
    float2 r; asm("mov.b64 {%0, %1}, %2;" : "=f"(r.x), "=f"(r.y) : "l"(v)); return r;
}

struct Ctx {
    float* Eb; float* BPb; int* Xb; int* U1Hb;
    u64* hs; u64* zs; float* red; float* nh; float* nbp; int* nx;
    const float* Wc2; const float* bc2;
    const float* Wb2; const float* bb2;
    const float* r_in;
    float* u_out; float* p_out;
    int b;
};

// ---------- layer 1 fused: [RB x 256] @ [256 x 512] ----------
// cols 0..255 -> relu -> hs (dup'd f32x2 pairs); cols 256..511 -> bp_out (global)
template<int RB>
__device__ void l1_chunk(const float* __restrict__ Ein, u64* zs, u64* hs,
                         float* __restrict__ bp_out, float* red)
{
    const int t = threadIdx.x;
    if constexpr (RB >= 8) {
        // stage acts, duplicated for f32x2
        for (int idx = t; idx < RB * 128; idx += THREADS) {
            float2 v = ((const float2*)Ein)[idx];
            ulonglong2 d; d.x = pk2(v.x, v.x); d.y = pk2(v.y, v.y);
            ((ulonglong2*)zs)[idx] = d;
        }
        __syncthreads();
        constexpr int NR = RB / 8;
        const int colq = t & 127;
        const int rg   = t >> 7;
        u64 acc[NR][2];
        #pragma unroll
        for (int r = 0; r < NR; r++) { acc[r][0] = 0ull; acc[r][1] = 0ull; }
        const ulonglong2* W = (const ulonglong2*)g_Wf + colq;
        #pragma unroll 2
        for (int k = 0; k < 256; k += 2) {
            ulonglong2 a2[NR];
            #pragma unroll
            for (int r = 0; r < NR; r++)
                a2[r] = *((const ulonglong2*)&zs[(rg + 8 * r) * 256 + k]);
            ulonglong2 w0 = __ldg(W + (size_t)k * 128);
            ulonglong2 w1 = __ldg(W + (size_t)(k + 1) * 128);
            #pragma unroll
            for (int r = 0; r < NR; r++) {
                fma2(acc[r][0], a2[r].x, w0.x); fma2(acc[r][1], a2[r].x, w0.y);
                fma2(acc[r][0], a2[r].y, w1.x); fma2(acc[r][1], a2[r].y, w1.y);
            }
        }
        const int col = colq * 4;
        float4 bias = *((const float4*)&g_bf[col]);
        #pragma unroll
        for (int r = 0; r < NR; r++) {
            int row = rg + 8 * r;
            float2 v0 = upk(acc[r][0]); float2 v1 = upk(acc[r][1]);
            float o0 = v0.x + bias.x, o1 = v0.y + bias.y;
            float o2 = v1.x + bias.z, o3 = v1.y + bias.w;
            if (col < 256) {
                float r0 = fmaxf(o0, 0.f), r1 = fmaxf(o1, 0.f);
                float r2 = fmaxf(o2, 0.f), r3 = fmaxf(o3, 0.f);
                ulonglong2 d0; d0.x = pk2(r0, r0); d0.y = pk2(r1, r1);
                ulonglong2 d1; d1.x = pk2(r2, r2); d1.y = pk2(r3, r3);
                *((ulonglong2*)&hs[row * 256 + col])     = d0;
                *((ulonglong2*)&hs[row * 256 + col + 2]) = d1;
            } else {
                *((float4*)&bp_out[row * HH + (col - 256)]) = make_float4(o0, o1, o2, o3);
            }
        }
        __syncthreads();
    } else {
        // RB = 2 or 4: split-K, acts direct from global
        constexpr int KP = 8 / RB;
        constexpr int KL = 256 / KP;
        const int colq = t & 127;
        const int g    = t >> 7;
        const int r    = g & (RB - 1);
        const int kp   = g / RB;
        const int k0   = kp * KL;
        const float* ac = Ein + r * 256;
        u64 acc0 = 0ull, acc1 = 0ull;
        const ulonglong2* W = (const ulonglong2*)g_Wf + colq;
        #pragma unroll 2
        for (int kb = 0; kb < KL; kb += 4) {
            float4 a4 = __ldg((const float4*)&ac[k0 + kb]);
            ulonglong2 w; u64 a;
            w = __ldg(W + (size_t)(k0 + kb + 0) * 128); a = pk2(a4.x, a4.x); fma2(acc0, a, w.x); fma2(acc1, a, w.y);
            w = __ldg(W + (size_t)(k0 + kb + 1) * 128); a = pk2(a4.y, a4.y); fma2(acc0, a, w.x); fma2(acc1, a, w.y);
            w = __ldg(W + (size_t)(k0 + kb + 2) * 128); a = pk2(a4.z, a4.z); fma2(acc0, a, w.x); fma2(acc1, a, w.y);
            w = __ldg(W + (size_t)(k0 + kb + 3) * 128); a = pk2(a4.w, a4.w); fma2(acc0, a, w.x); fma2(acc1, a, w.y);
        }
        float2 v0 = upk(acc0), v1 = upk(acc1);
        ((float4*)red)[g * 128 + colq] = make_float4(v0.x, v0.y, v1.x, v1.y);
        __syncthreads();
        for (int idx = t; idx < RB * 512; idx += THREADS) {
            int row = idx >> 9, col = idx & 511;
            float v = g_bf[col];
            #pragma unroll
            for (int q = 0; q < KP; q++) v += red[(q * RB + row) * 512 + col];
            if (col < 256) { float rl = fmaxf(v, 0.f); hs[row * 256 + col] = pk2(rl, rl); }
            else bp_out[row * HH + (col - 256)] = v;
        }
        __syncthreads();
    }
}

// ---------- layer 2: [RB x 256] @ [256 x 128] + b2 ----------
template<int RB>
__device__ void l2_chunk(const u64* hs, const float* __restrict__ W2,
                         const float* __restrict__ b2, float* __restrict__ Eout,
                         float* red)
{
    const int t = threadIdx.x;
    const int colq = t & 31;
    const int g    = t >> 5;
    const ulonglong2* W = (const ulonglong2*)W2 + colq;
    if constexpr (RB == 32) {
        const int row = g;
        u64 acc0 = 0ull, acc1 = 0ull;
        #pragma unroll 2
        for (int k = 0; k < 256; k += 2) {
            ulonglong2 a2 = *((const ulonglong2*)&hs[row * 256 + k]);
            ulonglong2 w0 = __ldg(W + (size_t)k * 32);
            ulonglong2 w1 = __ldg(W + (size_t)(k + 1) * 32);
            fma2(acc0, a2.x, w0.x); fma2(acc1, a2.x, w0.y);
            fma2(acc0, a2.y, w1.x); fma2(acc1, a2.y, w1.y);
        }
        float2 v0 = upk(acc0), v1 = upk(acc1);
        const int col = colq * 4;
        float4 bb = *((const float4*)&b2[col]);
        *((float4*)&Eout[row * 128 + col]) =
            make_float4(v0.x + bb.x, v0.y + bb.y, v1.x + bb.z, v1.y + bb.w);
        __syncthreads();
    } else {
        constexpr int KP = 32 / RB;
        constexpr int KL = 256 / KP;
        const int row = g & (RB - 1);
        const int kp  = g / RB;
        const int k0  = kp * KL;
        u64 acc0 = 0ull, acc1 = 0ull;
        #pragma unroll 2
        for (int k = k0; k < k0 + KL; k += 2) {
            ulonglong2 a2 = *((const ulonglong2*)&hs[row * 256 + k]);
            ulonglong2 w0 = __ldg(W + (size_t)k * 32);
            ulonglong2 w1 = __ldg(W + (size_t)(k + 1) * 32);
            fma2(acc0, a2.x, w0.x); fma2(acc1, a2.x, w0.y);
            fma2(acc0, a2.y, w1.x); fma2(acc1, a2.y, w1.y);
        }
        float2 v0 = upk(acc0), v1 = upk(acc1);
        ((float4*)red)[g * 32 + colq] = make_float4(v0.x, v0.y, v1.x, v1.y);
        __syncthreads();
        for (int idx = t; idx < RB * 128; idx += THREADS) {
            int row2 = idx >> 7, col = idx & 127;
            float v = __ldg(&b2[col]);
            #pragma unroll
            for (int q = 0; q < KP; q++) v += red[(q * RB + row2) * 128 + col];
            Eout[row2 * 128 + col] = v;
        }
        __syncthreads();
    }
}

__device__ void check_stage(Ctx& c, int l)
{
    const int half = 1 << (l - 1);
    const float* Ein = c.Eb + ((1 << l) - 1) * DD;
    float* Eout = c.Eb + ((1 << (l - 1)) - 1) * DD;
    float* BPl  = c.BPb + ((1 << (l - 1)) - 1) * HH;
    for (int done = 0; done < half; done += RBMAX) {
        int rbc = half - done; if (rbc > RBMAX) rbc = RBMAX;
        const float* ei = Ein + done * 256;
        float* eo = Eout + done * DD;
        float* bo = BPl + done * HH;
        switch (rbc) {
            case 32: l1_chunk<32>(ei, c.zs, c.hs, bo, c.red); l2_chunk<32>(c.hs, c.Wc2, c.bc2, eo, c.red); break;
            case 16: l1_chunk<16>(ei, c.zs, c.hs, bo, c.red); l2_chunk<16>(c.hs, c.Wc2, c.bc2, eo, c.red); break;
            case 8:  l1_chunk<8 >(ei, c.zs, c.hs, bo, c.red); l2_chunk<8 >(c.hs, c.Wc2, c.bc2, eo, c.red); break;
            case 4:  l1_chunk<4 >(ei, c.zs, c.hs, bo, c.red); l2_chunk<4 >(c.hs, c.Wc2, c.bc2, eo, c.red); break;
            default: l1_chunk<2 >(ei, c.zs, c.hs, bo, c.red); l2_chunk<2 >(c.hs, c.Wc2, c.bc2, eo, c.red); break;
        }
    }
}

__device__ void bit_stage(Ctx& c, int l)
{
    const int half = 1 << (l - 1);
    const int base = (1 << (l - 1)) - 1;
    float* Eout = c.Eb + base * DD;
    const float* BPl = c.BPb + base * HH;
    int* u1h = c.U1Hb + base;
    int* Xlm = c.Xb + base;
    __syncthreads();
    for (int i = threadIdx.x; i < half; i += THREADS) u1h[i] = Xlm[i];
    __syncthreads();
    for (int done = 0; done < half; done += RBMAX) {
        int rbc = half - done; if (rbc > RBMAX) rbc = RBMAX;
        for (int idx = threadIdx.x; idx < rbc * 256; idx += THREADS) {
            int row = idx >> 8, k = idx & 255;
            int u = u1h[done + row];
            float v = fmaxf(BPl[(done + row) * HH + k] + g_emb[u * HH + k], 0.f);
            c.hs[idx] = pk2(v, v);
        }
        __syncthreads();
        float* eo = Eout + done * DD;
        switch (rbc) {
            case 32: l2_chunk<32>(c.hs, c.Wb2, c.bb2, eo, c.red); break;
            case 16: l2_chunk<16>(c.hs, c.Wb2, c.bb2, eo, c.red); break;
            case 8:  l2_chunk<8 >(c.hs, c.Wb2, c.bb2, eo, c.red); break;
            case 4:  l2_chunk<4 >(c.hs, c.Wb2, c.bb2, eo, c.red); break;
            default: l2_chunk<2 >(c.hs, c.Wb2, c.bb2, eo, c.red); break;
        }
    }
}

__device__ __forceinline__ void combine_stage(Ctx& c, int l)
{
    int half = 1 << (l - 1);
    int* u1h = c.U1Hb + ((1 << (l - 1)) - 1);
    int* Xlm = c.Xb + ((1 << (l - 1)) - 1);
    int* Xl  = c.Xb + ((1 << l) - 1);
    __syncthreads();
    for (int i = threadIdx.x; i < half; i += THREADS) {
        int u2 = Xlm[i];
        Xl[2 * i]     = u1h[i] ^ u2;
        Xl[2 * i + 1] = u2;
    }
    __syncthreads();
}

// Fused level-1 node: check-L1 -> p_left -> left leaf -> bit-hidden -> p_right
// -> right leaf -> combine(1). No layer-2 GEMMs needed (dots vs W2@Wl).
__device__ void node1(Ctx& c, int n)
{
    const int t = threadIdx.x;
    const float* Ein = c.Eb + DD;   // level-1 array (2 rows) at base 1
    const int colq = t & 127;
    const int kp   = t >> 7;
    const int k0   = kp * 32;
    u64 acc0 = 0ull, acc1 = 0ull;
    const ulonglong2* W = (const ulonglong2*)g_Wf + colq;
    #pragma unroll
    for (int kb = 0; kb < 32; kb += 4) {
        float4 a4 = __ldg((const float4*)&Ein[k0 + kb]);
        ulonglong2 w; u64 a;
        w = __ldg(W + (size_t)(k0 + kb + 0) * 128); a = pk2(a4.x, a4.x); fma2(acc0, a, w.x); fma2(acc1, a, w.y);
        w = __ldg(W + (size_t)(k0 + kb + 1) * 128); a = pk2(a4.y, a4.y); fma2(acc0, a, w.x); fma2(acc1, a, w.y);
        w = __ldg(W + (size_t)(k0 + kb + 2) * 128); a = pk2(a4.z, a4.z); fma2(acc0, a, w.x); fma2(acc1, a, w.y);
        w = __ldg(W + (size_t)(k0 + kb + 3) * 128); a = pk2(a4.w, a4.w); fma2(acc0, a, w.x); fma2(acc1, a, w.y);
    }
    float2 v0 = upk(acc0), v1 = upk(acc1);
    ((float4*)c.red)[kp * 128 + colq] = make_float4(v0.x, v0.y, v1.x, v1.y);
    __syncthreads();
    if (t < 512) {
        float v = g_bf[t];
        #pragma unroll
        for (int q = 0; q < 8; q++) v += c.red[q * 512 + t];
        if (t < 256) c.nh[t] = fmaxf(v, 0.f);
        else c.nbp[t - 256] = v;
    }
    __syncthreads();
    if (t < 32) {
        float s = 0.f;
        #pragma unroll
        for (int j = 0; j < 8; j++) s = fmaf(c.nh[t + 32 * j], g_w2l[t + 32 * j], s);
        #pragma unroll
        for (int o = 16; o > 0; o >>= 1) s += __shfl_xor_sync(0xffffffffu, s, o);
        if (t == 0) {
            float p = 1.f / (1.f + expf(-(s + g_pbias[0])));
            int leaf = 2 * n;
            float rv = __ldg(&c.r_in[c.b * NBLK_C + leaf]);
            int f  = g_fenc[c.b * NBLK_C + leaf];
            int hd = (rv > p) ? 1 : 0;
            int x  = ((f == 2) || (fabsf(p - 0.5f) > 0.25f)) ? hd : f;
            *c.nx = x;
            c.u_out[c.b * NBLK_C + leaf] = (float)x;
            c.p_out[c.b * NBLK_C + leaf] = p;
        }
    }
    __syncthreads();
    int xL = *c.nx;
    if (t < 256)
        c.red[t] = fmaxf(c.nbp[t] + g_emb[xL * HH + t], 0.f) * g_w2l[256 + t];
    __syncthreads();
    if (t < 32) {
        float s = 0.f;
        #pragma unroll
        for (int j = 0; j < 8; j++) s += c.red[t + 32 * j];
        #pragma unroll
        for (int o = 16; o > 0; o >>= 1) s += __shfl_xor_sync(0xffffffffu, s, o);
        if (t == 0) {
            float p = 1.f / (1.f + expf(-(s + g_pbias[1])));
            int leaf = 2 * n + 1;
            float rv = __ldg(&c.r_in[c.b * NBLK_C + leaf]);
            int f  = g_fenc[c.b * NBLK_C + leaf];
            int hd = (rv > p) ? 1 : 0;
            int xR = ((f == 2) || (fabsf(p - 0.5f) > 0.25f)) ? hd : f;
            c.u_out[c.b * NBLK_C + leaf] = (float)xR;
            c.p_out[c.b * NBLK_C + leaf] = p;
            c.Xb[1] = xL ^ xR;   // combine(1)
            c.Xb[2] = xR;
        }
    }
    __syncthreads();
}

__global__ void __launch_bounds__(THREADS, 1)
sc_main(const float* r_in,
        const float* Wc2, const float* bc2,
        const float* Wb2, const float* bb2,
        float* out)
{
    extern __shared__ __align__(16) char smraw[];
    Ctx c;
    c.hs  = (u64*)smraw;                     // 64 KB
    c.zs  = c.hs + 32 * 256;                 // 64 KB
    c.red = (float*)(c.zs + 32 * 256);       // 16 KB
    c.nh  = c.red + 4096;
    c.nbp = c.nh + 256;
    c.nx  = (int*)(c.nbp + 256);
    c.b = blockIdx.x;
    c.Eb   = g_E   + c.b * 511 * DD;
    c.BPb  = g_BP  + c.b * 255 * HH;
    c.Xb   = g_X   + c.b * 511;
    c.U1Hb = g_U1H + c.b * 256;
    c.Wc2 = Wc2; c.bc2 = bc2;
    c.Wb2 = Wb2; c.bb2 = bb2;
    c.r_in  = r_in;
    c.u_out = out + 2 * SEC;
    c.p_out = out + 3 * SEC;

    for (int l = 8; l >= 2; l--) check_stage(c, l);
    for (int n = 0; n < 128; n++) {
        node1(c, n);
        if (n == 127) break;
        int l = 2;
        while ((n >> (l - 2)) & 1) { combine_stage(c, l); l++; }
        bit_stage(c, l);
        for (int ld = l - 1; ld >= 2; ld--) check_stage(c, ld);
    }
    for (int l = 2; l <= 8; l++) combine_stage(c, l);

    int* X8 = c.Xb + 255;
    for (int i = threadIdx.x; i < NBLK_C; i += THREADS)
        out[c.b * NBLK_C + i] = (float)X8[i];
}

// ---- per-batch init ----
__global__ void sc_setup(const int* info_bits, const float* r_in, const int* info_set,
                         const float* E_obs, float* out)
{
    int b = blockIdx.x, t = threadIdx.x;
    for (int j = t; j < NBLK_C; j += blockDim.x) {
        g_fenc[b * NBLK_C + j] = 2;
        out[1 * SEC + b * NBLK_C + j] = 1.0f;
        out[4 * SEC + b * NBLK_C + j] = r_in[b * NBLK_C + j];
    }
    __syncthreads();
    for (int k = t; k < 128; k += blockDim.x) {
        int pos = info_set[k];
        g_fenc[b * NBLK_C + pos] = info_bits[b * 128 + k];
        out[1 * SEC + b * NBLK_C + pos] = 2.0f;
    }
    for (int idx = t; idx < 256 * DD; idx += blockDim.x) {
        int i = idx >> 7, k = idx & (DD - 1);
        g_E[b * 511 * DD + (255 + i) * DD + k] = E_obs[2 * DD + k];
    }
}

// ---- parallel weight prep ----
__global__ void sc_prep(const float* Wc1, const float* bc1,
                        const float* Wb1, const float* bb1,
                        const float* E_lab,
                        const float* Wc2, const float* bc2,
                        const float* Wb2, const float* bb2,
                        const float* Wl, const float* bl)
{
    int tid = blockIdx.x * blockDim.x + threadIdx.x;   // 64*512 = 32768 threads
    {   // g_Wf: 32768 float4 copies
        int k = tid >> 7, c4 = (tid & 127) * 4;
        float4 v;
        if (c4 < 256) v = *((const float4*)&Wc1[k * 256 + c4]);
        else          v = *((const float4*)&Wb1[k * 256 + (c4 - 256)]);
        *((float4*)&g_Wf[k * 512 + c4]) = v;
    }
    if (tid < 512) g_bf[tid] = (tid < 256) ? bc1[tid] : bb1[tid - 256];
    if (tid >= 512 && tid < 1024) {
        int cidx = tid - 512;
        const float* W2 = (cidx < 256) ? Wc2 : Wb2;
        int k = cidx & 255;
        float s = 0.f;
        for (int d = 0; d < 128; d++) s += W2[k * 128 + d] * Wl[d];
        g_w2l[cidx] = s;
    }
    if (tid >= 1024 && tid < 1536) {
        int cidx = tid - 1024; int u = cidx >> 8, j = cidx & 255;
        float s = 0.f;
        for (int d = 0; d < 128; d++) s += E_lab[u * 128 + d] * Wb1[(256 + d) * 256 + j];
        g_emb[u * HH + j] = s;
    }
    if (tid == 1536 || tid == 1537) {
        int u = tid - 1536;
        const float* b2 = u ? bb2 : bc2;
        float s = bl[0];
        for (int d = 0; d < 128; d++) s += b2[d] * Wl[d];
        g_pbias[u] = s;
    }
}

extern "C" void kernel_launch(void* const* d_in, const int* in_sizes, int n_in,
                              void* d_out, int out_size)
{
    const int*   info_bits = (const int*)  d_in[0];
    const float* r_in      = (const float*)d_in[1];
    const int*   info_set  = (const int*)  d_in[2];
    const float* E_obs     = (const float*)d_in[3];
    const float* E_lab     = (const float*)d_in[4];
    const float* Wc1 = (const float*)d_in[5];
    const float* bc1 = (const float*)d_in[6];
    const float* Wc2 = (const float*)d_in[7];
    const float* bc2 = (const float*)d_in[8];
    const float* Wb1 = (const float*)d_in[9];
    const float* bb1 = (const float*)d_in[10];
    const float* Wb2 = (const float*)d_in[11];
    const float* bb2 = (const float*)d_in[12];
    const float* Wl  = (const float*)d_in[13];
    const float* bl  = (const float*)d_in[14];
    float* out = (float*)d_out;

    const int smem = (32 * 256 * 8) * 2 + 4096 * 4 + 2 * 256 * 4 + 16;  // ~147.5 KB
    cudaFuncSetAttribute(sc_main, cudaFuncAttributeMaxDynamicSharedMemorySize, smem);

    sc_prep<<<64, 512>>>(Wc1, bc1, Wb1, bb1, E_lab, Wc2, bc2, Wb2, bb2, Wl, bl);
    sc_setup<<<BATCH, 256>>>(info_bits, r_in, info_set, E_obs, out);
    sc_main<<<BATCH, THREADS, smem>>>(r_in, Wc2, bc2, Wb2, bb2, out);
}